// round 15
// baseline (speedup 1.0000x reference)
#include <cuda_runtime.h>
#include <cuda_fp16.h>
#include <math.h>
#include <stdint.h>

// ---------------- problem constants ----------------
#define LNUM 4
#define BB   4
#define TT   2048
#define DD   1024
#define HH   1024
#define FF   256
#define MTOT (BB*TT)          // 8192
#define NCHUNK 16
#define CL   (TT/NCHUNK)      // 128

// ---------------- mma GEMM config: 128m x 256n tile, 8 warps (2x4) ----------------
#define BKC   64                      // k elements per stage
#define MATB  16384                   // 128 rows x 128B
#define STAGEB (4*MATB)               // Ah(16K), Al(16K), W(32K) = 64 KB
#define NSTG  2
#define SMEMB 133120                  // >= 2*STAGEB (128K) and >= scan staging (130K)
#define QS    132                     // fused-GLU smem staging stride (floats)
#define SS    260                     // Bu-scan smem staging stride (floats)

typedef __half f16;

// ---------------- scratch (device globals; no allocs allowed) ----------------
__device__ __align__(16) f16   g_xn_h[MTOT*DD];
__device__ __align__(16) f16   g_xn_l[MTOT*DD];
__device__ __align__(16) f16   g_in_h[MTOT*FF];
__device__ __align__(16) f16   g_in_l[MTOT*FF];
__device__ __align__(16) float g_bu[MTOT*2*HH];
__device__ __align__(16) f16   g_hs_h[MTOT*2*HH];
__device__ __align__(16) f16   g_y_h[MTOT*DD];
__device__ __align__(16) f16   g_win[DD*FF];
__device__ __align__(16) f16   g_bw[LNUM*2*HH*DD];
__device__ __align__(16) f16   g_cw[LNUM*DD*2*HH];
__device__ __align__(16) f16   g_gw[LNUM*2*DD*DD];
__device__ float g_lam_re[LNUM*HH];
__device__ float g_lam_im[LNUM*HH];
__device__ float g_gam  [LNUM*HH];
__device__ float g_sum_re[BB*NCHUNK*HH];
__device__ float g_sum_im[BB*NCHUNK*HH];
__device__ float g_car_re[BB*NCHUNK*HH];
__device__ float g_car_im[BB*NCHUNK*HH];

// ---------------- helpers ----------------
__device__ __forceinline__ float gelu_exact(float v) {
    return 0.5f * v * (1.0f + erff(v * 0.70710678118654752f));
}
__device__ __forceinline__ void split2h(float v, f16& h, f16& l) {
    h = __float2half_rn(v);
    l = __float2half_rn(v - __half2float(h));
}
__device__ __forceinline__ void cp16(uint32_t d, const void* s) {
    asm volatile("cp.async.cg.shared.global [%0], [%1], 16;" :: "r"(d), "l"(s));
}
__device__ __forceinline__ void cpcommit() {
    asm volatile("cp.async.commit_group;" ::: "memory");
}
template<int N> __device__ __forceinline__ void cpwait() {
    asm volatile("cp.async.wait_group %0;" :: "n"(N) : "memory");
}
__device__ __forceinline__ void mma_f16(float* c, const uint32_t* a,
                                        uint32_t b0, uint32_t b1) {
    asm volatile("mma.sync.aligned.m16n8k16.row.col.f32.f16.f16.f32 "
        "{%0,%1,%2,%3}, {%4,%5,%6,%7}, {%8,%9}, {%0,%1,%2,%3};"
        : "+f"(c[0]), "+f"(c[1]), "+f"(c[2]), "+f"(c[3])
        : "r"(a[0]), "r"(a[1]), "r"(a[2]), "r"(a[3]), "r"(b0), "r"(b1));
}
__device__ __forceinline__ void ldm4(uint32_t* r, uint32_t a) {
    asm volatile("ldmatrix.sync.aligned.m8n8.x4.shared.b16 {%0,%1,%2,%3}, [%4];"
        : "=r"(r[0]), "=r"(r[1]), "=r"(r[2]), "=r"(r[3]) : "r"(a));
}

// swizzled chunk offset: row r (128B rows), 16B-chunk c (0..7)
__device__ __forceinline__ uint32_t swz(int r, int c) {
    return (uint32_t)(r * 128 + ((c ^ (r & 7)) << 4));
}

// load one K-stage: Ah (+Al if two) rows m0..m0+127, W rows n0..n0+255
__device__ __forceinline__ void ldstage(uint32_t sb, int slot,
        const f16* Ah, const f16* Al, int lda,
        const f16* W, int ldw,
        int m0, int n0, int kb, int tid, bool two) {
    uint32_t st = sb + (uint32_t)slot * STAGEB;
    #pragma unroll
    for (int j = 0; j < 4; j++) {           // A: 128 rows x 8 chunks
        int chunk = tid + j * 256;
        int row   = chunk >> 3;
        int c     = chunk & 7;
        uint32_t d = st + swz(row, c);
        int ke = kb + c * 8;
        cp16(d, Ah + (size_t)(m0+row)*lda + ke);
        if (two) cp16(d + MATB, Al + (size_t)(m0+row)*lda + ke);
    }
    #pragma unroll
    for (int j = 0; j < 8; j++) {           // W: 256 rows x 8 chunks
        int chunk = tid + j * 256;
        int row   = chunk >> 3;
        int c     = chunk & 7;
        cp16(st + 2*MATB + swz(row, c), W + (size_t)(n0+row)*ldw + kb + c * 8);
    }
    cpcommit();
}

// ---------------- split-fp16 tensor-core GEMM (128m x 256n) ----------------
// epi 0: Cf = acc + bias0(n)
// epi 2: Ch = half(gelu(acc + (epi_mh+epi_ml)[m,n]*epi_n[n]))
// epi 3: fused GLU: W interleaved [w1|w2] per 128 rows; x += (a+b1)*sigmoid(q+b2)
// epi 4: Bu + chunk-scan: W interleaved [re|im] per 128 rows; Cf = acc*gamma, scan->g_sum
__global__ __launch_bounds__(256, 1)
void gemm_mma(const f16* __restrict__ Ah, const f16* __restrict__ Al, int lda,
              const f16* __restrict__ W,
              float* __restrict__ Cf, f16* __restrict__ Ch,
              int ldc, int K, int epi,
              const float* __restrict__ bias0, const float* __restrict__ bias1,
              const f16* __restrict__ epi_mh, const f16* __restrict__ epi_ml,
              const float* __restrict__ epi_n, int loff) {
    extern __shared__ __align__(16) char smc[];
    uint32_t sb = (uint32_t)__cvta_generic_to_shared(smc);
    const int tid  = threadIdx.x;
    const int wid  = tid >> 5, lane = tid & 31;
    const int g    = lane >> 2, t2 = lane & 3;
    const int warpM = wid & 1;          // 0..1 (64 rows each)
    const int warpN = wid >> 1;         // 0..3 (64 cols each)
    const int m0 = blockIdx.y * 128;
    const int n0 = blockIdx.x * 256;
    const int NCH = K / BKC;
    const bool twopass = (Al != nullptr);

    // ldmatrix per-lane rows / chunk bases
    const int grp = lane >> 3, rr = lane & 7;
    const int cA0 = grp >> 1;
    const int cB0 = grp & 1;
    int rA[4], rB[4];
    #pragma unroll
    for (int mt = 0; mt < 4; mt++) rA[mt] = warpM*64 + mt*16 + rr + (grp & 1)*8;
    #pragma unroll
    for (int ntp = 0; ntp < 4; ntp++) rB[ntp] = warpN*64 + ntp*16 + rr + (grp >> 1)*8;

    float acc[4][8][4];
    #pragma unroll
    for (int i = 0; i < 4; i++)
        #pragma unroll
        for (int j = 0; j < 8; j++)
            #pragma unroll
            for (int q = 0; q < 4; q++) acc[i][j][q] = 0.f;

    ldstage(sb, 0, Ah, Al, lda, W, K, m0, n0, 0,   tid, twopass);
    ldstage(sb, 1, Ah, Al, lda, W, K, m0, n0, BKC, tid, twopass);
    cpwait<1>();
    __syncthreads();

    for (int t = 0; t < NCH; t++) {
        const int slot = t & 1;
        uint32_t st   = sb + (uint32_t)slot * STAGEB;
        uint32_t Ah_s = st, Al_s = st + MATB, W_s = st + 2*MATB;

        #pragma unroll
        for (int kh = 0; kh < 4; kh++) {
            uint32_t ah[4][4], al[4][4];
            #pragma unroll
            for (int mt = 0; mt < 4; mt++) {
                uint32_t ao = swz(rA[mt], cA0 + 2*kh);
                ldm4(ah[mt], Ah_s + ao);
                if (twopass) ldm4(al[mt], Al_s + ao);
            }
            #pragma unroll
            for (int ntp = 0; ntp < 4; ntp++) {
                uint32_t bo = swz(rB[ntp], cB0 + 2*kh);
                uint32_t bh[4];
                ldm4(bh, W_s + bo);
                #pragma unroll
                for (int sub = 0; sub < 2; sub++) {
                    int nt = ntp*2 + sub;
                    uint32_t b0 = bh[sub*2], b1 = bh[sub*2+1];
                    mma_f16(acc[0][nt], ah[0], b0, b1);
                    mma_f16(acc[1][nt], ah[1], b0, b1);
                    mma_f16(acc[2][nt], ah[2], b0, b1);
                    mma_f16(acc[3][nt], ah[3], b0, b1);
                    if (twopass) {
                        mma_f16(acc[0][nt], al[0], b0, b1);
                        mma_f16(acc[1][nt], al[1], b0, b1);
                        mma_f16(acc[2][nt], al[2], b0, b1);
                        mma_f16(acc[3][nt], al[3], b0, b1);
                    }
                }
            }
        }

        __syncthreads();   // WAR: finish reads before refilling this slot
        if (t + 2 < NCH)
            ldstage(sb, slot, Ah, Al, lda, W, K, m0, n0, (t+2)*BKC, tid, twopass);
        else
            cpcommit();
        cpwait<1>();
        __syncthreads();   // publish stage t+1
    }

    // ---- epilogue ----
    if (epi == 4) {
        // Bu (gamma, interleaved [re|im] per 128 cols) + chunk scan over 128 rows
        float* sm = (float*)smc;
        #pragma unroll
        for (int mt = 0; mt < 4; mt++)
            #pragma unroll
            for (int nt = 0; nt < 8; nt++) {
                int r0 = warpM*64 + mt*16 + g, r1 = r0 + 8;
                int nn = warpN*64 + nt*8 + t2*2;
                int hI = (blockIdx.x*2 + (nn >> 7))*64 + (nn & 63);
                float e0 = epi_n[hI], e1 = epi_n[hI + 1];
                float c0 = acc[mt][nt][0]*e0, c1 = acc[mt][nt][1]*e1;
                float c2 = acc[mt][nt][2]*e0, c3 = acc[mt][nt][3]*e1;
                *(float2*)(Cf + (size_t)(m0 + r0) * ldc + n0 + nn) = make_float2(c0, c1);
                *(float2*)(Cf + (size_t)(m0 + r1) * ldc + n0 + nn) = make_float2(c2, c3);
                sm[r0*SS + nn] = c0;  sm[r0*SS + nn + 1] = c1;
                sm[r1*SS + nn] = c2;  sm[r1*SS + nn + 1] = c3;
            }
        __syncthreads();
        if (tid < 128) {
            int jl = tid >> 6;                      // 0/1: which 128-col block
            int hc = tid & 63;
            int h = (blockIdx.x*2 + jl)*64 + hc;
            int creb = jl*128 + hc;
            float lre = g_lam_re[loff + h], lim = g_lam_im[loff + h];
            float are = 0.f, aim = 0.f;
            #pragma unroll 4
            for (int r = 0; r < 128; r++) {
                float ure = sm[r*SS + creb];
                float uim = sm[r*SS + creb + 64];
                float nr = fmaf(are, lre, fmaf(-aim, lim, ure));
                float ni = fmaf(are, lim, fmaf(aim, lre, uim));
                are = nr; aim = ni;
            }
            int b = m0 >> 11;
            int chunk = (m0 & (TT - 1)) >> 7;
            int o = (b * NCHUNK + chunk) * HH + h;
            g_sum_re[o] = are; g_sum_im[o] = aim;
        }
        return;
    }
    if (epi == 3) {
        // fused GLU: per 128-row block of W: [w1 x64 | w2 x64]; out cols bx*128..+127
        const int co = blockIdx.x * 128;
        float* qs = (float*)smc;
        const bool isq = (warpN & 1);   // warps with nn&64 set hold w2 (q)
        if (isq) {
            #pragma unroll
            for (int mt = 0; mt < 4; mt++)
                #pragma unroll
                for (int nt = 0; nt < 8; nt++) {
                    int r0 = warpM*64 + mt*16 + g, r1 = r0 + 8;
                    int nn = warpN*64 + nt*8 + t2*2;
                    int oc = ((nn >> 7) << 6) + (nn & 63);
                    float bb0 = bias1[co + oc], bb1 = bias1[co + oc + 1];
                    qs[r0*QS + oc]     = acc[mt][nt][0] + bb0;
                    qs[r0*QS + oc + 1] = acc[mt][nt][1] + bb1;
                    qs[r1*QS + oc]     = acc[mt][nt][2] + bb0;
                    qs[r1*QS + oc + 1] = acc[mt][nt][3] + bb1;
                }
        }
        __syncthreads();
        if (!isq) {
            #pragma unroll
            for (int mt = 0; mt < 4; mt++)
                #pragma unroll
                for (int nt = 0; nt < 8; nt++) {
                    int r0 = warpM*64 + mt*16 + g, r1 = r0 + 8;
                    int nn = warpN*64 + nt*8 + t2*2;
                    int oc = ((nn >> 7) << 6) + (nn & 63);
                    float bb0 = bias0[co + oc], bb1 = bias0[co + oc + 1];
                    float a00 = acc[mt][nt][0] + bb0, a01 = acc[mt][nt][1] + bb1;
                    float a10 = acc[mt][nt][2] + bb0, a11 = acc[mt][nt][3] + bb1;
                    float q00 = qs[r0*QS + oc], q01 = qs[r0*QS + oc + 1];
                    float q10 = qs[r1*QS + oc], q11 = qs[r1*QS + oc + 1];
                    float* x0 = Cf + (size_t)(m0 + r0) * DD + co + oc;
                    float* x1 = Cf + (size_t)(m0 + r1) * DD + co + oc;
                    float2 v0 = *(float2*)x0, v1 = *(float2*)x1;
                    v0.x = fmaf(a00, 1.f/(1.f + expf(-q00)), v0.x);
                    v0.y = fmaf(a01, 1.f/(1.f + expf(-q01)), v0.y);
                    v1.x = fmaf(a10, 1.f/(1.f + expf(-q10)), v1.x);
                    v1.y = fmaf(a11, 1.f/(1.f + expf(-q11)), v1.y);
                    *(float2*)x0 = v0;
                    *(float2*)x1 = v1;
                }
        }
        return;
    }
    #pragma unroll
    for (int mt = 0; mt < 4; mt++) {
        #pragma unroll
        for (int nt = 0; nt < 8; nt++) {
            int row0 = m0 + warpM*64 + mt*16 + g;
            int row1 = row0 + 8;
            int col  = n0 + warpN*64 + nt*8 + t2*2;
            float c0 = acc[mt][nt][0], c1 = acc[mt][nt][1];
            float c2 = acc[mt][nt][2], c3 = acc[mt][nt][3];
            if (epi == 0) {
                float b0v = bias0[col], b1v = bias0[col + 1];
                *(float2*)(Cf + (size_t)row0 * ldc + col) = make_float2(c0 + b0v, c1 + b1v);
                *(float2*)(Cf + (size_t)row1 * ldc + col) = make_float2(c2 + b0v, c3 + b1v);
            } else {
                float d0 = epi_n[col], d1 = epi_n[col+1];
                __half2 xh0 = *(const __half2*)(epi_mh + (size_t)row0 * DD + col);
                __half2 xl0 = *(const __half2*)(epi_ml + (size_t)row0 * DD + col);
                __half2 xh1 = *(const __half2*)(epi_mh + (size_t)row1 * DD + col);
                __half2 xl1 = *(const __half2*)(epi_ml + (size_t)row1 * DD + col);
                float m00 = __half2float(xh0.x) + __half2float(xl0.x);
                float m01 = __half2float(xh0.y) + __half2float(xl0.y);
                float m10 = __half2float(xh1.x) + __half2float(xl1.x);
                float m11 = __half2float(xh1.y) + __half2float(xl1.y);
                float v0 = gelu_exact(c0 + m00 * d0);
                float v1 = gelu_exact(c1 + m01 * d1);
                float v2 = gelu_exact(c2 + m10 * d0);
                float v3 = gelu_exact(c3 + m11 * d1);
                __half2 ph0(__float2half_rn(v0), __float2half_rn(v1));
                __half2 ph1(__float2half_rn(v2), __float2half_rn(v3));
                *(uint32_t*)(Ch + (size_t)row0 * ldc + col) = *(uint32_t*)&ph0;
                *(uint32_t*)(Ch + (size_t)row1 * ldc + col) = *(uint32_t*)&ph1;
            }
        }
    }
}

// ---------------- parameter prep ----------------
__global__ void prep_kernel(const float* __restrict__ nu_log,
                            const float* __restrict__ theta_log) {
    int i = blockIdx.x * blockDim.x + threadIdx.x;
    float nu = expf(nu_log[i]);
    float th = expf(theta_log[i]);
    float r  = expf(-nu);
    g_lam_re[i] = r * cosf(th);
    g_lam_im[i] = r * sinf(th);
    g_gam[i]    = sqrtf(1.0f - expf(-2.0f * nu) + 1e-5f);
}

// ---------------- input splitter ----------------
__global__ void split_in_kernel(const float* __restrict__ s) {
    int i = blockIdx.x * 256 + threadIdx.x;
    f16 h, l;
    split2h(s[i], h, l);
    g_in_h[i] = h; g_in_l[i] = l;
}

// ---------------- all-weights converter (single fp16 plane) ----------------
#define NW  (DD*FF)
#define NB  (LNUM*2*HH*DD)
#define NC  (LNUM*DD*2*HH)
#define NG  (LNUM*2*DD*DD)
__global__ void split_wts_kernel(const float* __restrict__ W_in,
                                 const float* __restrict__ B_re,
                                 const float* __restrict__ B_im,
                                 const float* __restrict__ C_re,
                                 const float* __restrict__ C_im,
                                 const float* __restrict__ w1,
                                 const float* __restrict__ w2) {
    int idx = blockIdx.x * 256 + threadIdx.x;
    float v;
    if (idx < NW) {
        g_win[idx] = __float2half_rn(W_in[idx]);
        return;
    }
    idx -= NW;
    if (idx < NB) {
        int l_ = idx / (2*HH*DD);
        int t  = idx - l_ * (2*HH*DD);
        int np = t >> 10, c = t & 1023;
        int j = np >> 7, o = np & 127;
        if (o < 64) v = B_re[(size_t)l_*HH*DD + (j*64 + o)*DD + c];
        else        v = B_im[(size_t)l_*HH*DD + (j*64 + o - 64)*DD + c];
        g_bw[idx] = __float2half_rn(v);
        return;
    }
    idx -= NB;
    if (idx < NC) {
        int l_ = idx / (DD*2*HH);
        int t  = idx - l_ * (DD*2*HH);
        int r  = t >> 11, k = t & 2047;
        int j = k >> 7, o = k & 127;
        if (o < 64) v = C_re[(size_t)l_*DD*HH + r*HH + (j*64 + o)];
        else        v = -C_im[(size_t)l_*DD*HH + r*HH + (j*64 + o - 64)];
        g_cw[idx] = __float2half_rn(v);
        return;
    }
    idx -= NC;
    {
        int l_ = idx / (2*DD*DD);
        int t  = idx - l_ * (2*DD*DD);
        int np = t >> 10, c = t & 1023;
        int blk = np >> 7, off = np & 127;
        if (off < 64) v = w1[(size_t)l_*DD*DD + (blk*64 + off)*DD + c];
        else          v = w2[(size_t)l_*DD*DD + (blk*64 + off - 64)*DD + c];
        g_gw[idx] = __float2half_rn(v);
    }
}

// ---------------- layernorm (fp16 split outputs only) ----------------
__global__ void ln_kernel(const float* __restrict__ x,
                          const float* __restrict__ sc,
                          const float* __restrict__ bi,
                          f16* __restrict__ oh, f16* __restrict__ ol) {
    __shared__ float red[16];
    int row = blockIdx.x;
    int tid = threadIdx.x;
    const float* xr = x + (size_t)row * DD;
    float4 v = *(const float4*)(xr + tid * 4);
    float s  = v.x + v.y + v.z + v.w;
    float ss = v.x*v.x + v.y*v.y + v.z*v.z + v.w*v.w;
    #pragma unroll
    for (int off = 16; off; off >>= 1) {
        s  += __shfl_xor_sync(0xffffffffu, s,  off);
        ss += __shfl_xor_sync(0xffffffffu, ss, off);
    }
    int wid = tid >> 5;
    if ((tid & 31) == 0) { red[wid] = s; red[8 + wid] = ss; }
    __syncthreads();
    float S = 0.f, SS_ = 0.f;
    #pragma unroll
    for (int w = 0; w < 8; w++) { S += red[w]; SS_ += red[8 + w]; }
    float mu  = S * (1.0f / DD);
    float var = SS_ * (1.0f / DD) - mu * mu;
    float rstd = rsqrtf(var + 1e-5f);
    float4 s4 = *(const float4*)(sc + tid * 4);
    float4 b4 = *(const float4*)(bi + tid * 4);
    float ov[4];
    ov[0] = (v.x - mu) * rstd * s4.x + b4.x;
    ov[1] = (v.y - mu) * rstd * s4.y + b4.y;
    ov[2] = (v.z - mu) * rstd * s4.z + b4.z;
    ov[3] = (v.w - mu) * rstd * s4.w + b4.w;
    f16 h[4], l[4];
    #pragma unroll
    for (int j = 0; j < 4; j++) split2h(ov[j], h[j], l[j]);
    *(uint2*)(oh + (size_t)row * DD + tid * 4) = *(uint2*)h;
    *(uint2*)(ol + (size_t)row * DD + tid * 4) = *(uint2*)l;
}

// ---------------- scan carry (over chunk summaries) ----------------
__global__ void scan_carry_kernel(int loff) {
    int idx = blockIdx.x * blockDim.x + threadIdx.x;
    int b = idx >> 10, h = idx & (HH - 1);
    float lre = g_lam_re[loff + h], lim = g_lam_im[loff + h];
    float pre = lre, pim = lim;
    #pragma unroll
    for (int i = 0; i < 7; i++) {
        float nr = pre*pre - pim*pim;
        float ni = 2.f*pre*pim;
        pre = nr; pim = ni;
    }
    float cre = 0.f, cim = 0.f;
    #pragma unroll
    for (int c = 0; c < NCHUNK; c++) {
        int o = (b * NCHUNK + c) * HH + h;
        g_car_re[o] = cre; g_car_im[o] = cim;
        float sre = g_sum_re[o], sim = g_sum_im[o];
        float nr = cre*pre - cim*pim + sre;
        float ni = cre*pim + cim*pre + sim;
        cre = nr; cim = ni;
    }
}

// ---------------- scan apply (interleaved bu layout; single fp16 hs plane) ----------------
__global__ void scan_apply_kernel(const float* __restrict__ bu,
                                  f16* __restrict__ hsh, int loff) {
    int h = blockIdx.x * blockDim.x + threadIdx.x;
    int c = blockIdx.y, b = blockIdx.z;
    float lre = g_lam_re[loff + h], lim = g_lam_im[loff + h];
    int o = (b * NCHUNK + c) * HH + h;
    float are = g_car_re[o], aim = g_car_im[o];
    int col = ((h >> 6) << 7) + (h & 63);   // interleaved re col; im at +64
    size_t base = ((size_t)(b * TT + c * CL)) * (2 * HH) + col;
    #pragma unroll 4
    for (int j = 0; j < CL; j++) {
        float ure = bu[base], uim = bu[base + 64];
        float nr = fmaf(are, lre, fmaf(-aim, lim, ure));
        float ni = fmaf(are, lim, fmaf(aim, lre, uim));
        are = nr; aim = ni;
        hsh[base]      = __float2half_rn(are);
        hsh[base + 64] = __float2half_rn(aim);
        base += 2 * HH;
    }
}

// ---------------- launch ----------------
extern "C" void kernel_launch(void* const* d_in, const int* in_sizes, int n_in,
                              void* d_out, int out_size) {
    const float* inputs    = (const float*)d_in[0];
    const float* W_in      = (const float*)d_in[1];
    const float* b_in      = (const float*)d_in[2];
    const float* nu_log    = (const float*)d_in[3];
    const float* theta_log = (const float*)d_in[4];
    const float* B_re      = (const float*)d_in[5];
    const float* B_im      = (const float*)d_in[6];
    const float* C_re      = (const float*)d_in[7];
    const float* C_im      = (const float*)d_in[8];
    const float* D_diag    = (const float*)d_in[9];
    const float* ln_scale  = (const float*)d_in[10];
    const float* ln_bias   = (const float*)d_in[11];
    const float* w1        = (const float*)d_in[12];
    const float* b1        = (const float*)d_in[13];
    const float* w2        = (const float*)d_in[14];
    const float* b2        = (const float*)d_in[15];
    float* x = (float*)d_out;

    cudaFuncSetAttribute(gemm_mma, cudaFuncAttributeMaxDynamicSharedMemorySize, SMEMB);

    float *p_bu, *p_gam;
    f16 *p_xnh, *p_xnl, *p_inh, *p_inl, *p_hsh, *p_yh;
    f16 *p_win, *p_bw, *p_cw, *p_gw;
    cudaGetSymbolAddress((void**)&p_bu,  g_bu);
    cudaGetSymbolAddress((void**)&p_gam, g_gam);
    cudaGetSymbolAddress((void**)&p_xnh, g_xn_h);
    cudaGetSymbolAddress((void**)&p_xnl, g_xn_l);
    cudaGetSymbolAddress((void**)&p_inh, g_in_h);
    cudaGetSymbolAddress((void**)&p_inl, g_in_l);
    cudaGetSymbolAddress((void**)&p_hsh, g_hs_h);
    cudaGetSymbolAddress((void**)&p_yh,  g_y_h);
    cudaGetSymbolAddress((void**)&p_win, g_win);
    cudaGetSymbolAddress((void**)&p_bw,  g_bw);
    cudaGetSymbolAddress((void**)&p_cw,  g_cw);
    cudaGetSymbolAddress((void**)&p_gw,  g_gw);

    // params, split inputs, convert all weights
    prep_kernel<<<(LNUM * HH) / 256, 256>>>(nu_log, theta_log);
    split_in_kernel<<<(MTOT*FF)/256, 256>>>(inputs);
    split_wts_kernel<<<(NW + NB + NC + NG)/256, 256>>>(
        W_in, B_re, B_im, C_re, C_im, w1, w2);

    // input projection: x = inputs @ W_in^T + b_in  (2-pass)
    gemm_mma<<<dim3(DD/256, MTOT/128), 256, SMEMB>>>(
        p_inh, p_inl, FF, p_win,
        x, nullptr, DD, FF, 0,
        b_in, nullptr, nullptr, nullptr, nullptr, 0);

    for (int l = 0; l < LNUM; l++) {
        // layernorm -> fp16 split planes
        ln_kernel<<<MTOT, 256>>>(x, ln_scale + l*DD, ln_bias + l*DD, p_xnh, p_xnl);

        // Bu = gamma * (xn @ Bw^T) with fused chunk-scan summaries (2-pass)
        gemm_mma<<<dim3(2*HH/256, MTOT/128), 256, SMEMB>>>(
            p_xnh, p_xnl, DD,
            p_bw + (size_t)l*2*HH*DD,
            p_bu, nullptr, 2*HH, DD, 4,
            nullptr, nullptr, nullptr, nullptr, p_gam + l*HH, l*HH);

        scan_carry_kernel<<<(BB*HH)/256, 256>>>(l*HH);
        scan_apply_kernel<<<dim3(HH/256, NCHUNK, BB), 256>>>(p_bu, p_hsh, l*HH);

        // y = gelu( hs @ Cw^T + xn * D_diag )  (1-pass, fp16 out)
        gemm_mma<<<dim3(DD/256, MTOT/128), 256, SMEMB>>>(
            p_hsh, nullptr, 2*HH,
            p_cw + (size_t)l*DD*2*HH,
            nullptr, p_yh, DD, 2*HH, 2,
            nullptr, nullptr, p_xnh, p_xnl, D_diag + l*DD, 0);

        // fused GLU + residual (1-pass): x += (y@w1^T + b1) * sigmoid(y@w2^T + b2)
        gemm_mma<<<dim3(2*DD/256, MTOT/128), 256, SMEMB>>>(
            p_yh, nullptr, DD,
            p_gw + (size_t)l*2*DD*DD,
            x, nullptr, DD, DD, 3,
            b1 + l*DD, b2 + l*DD, nullptr, nullptr, nullptr, 0);
    }
    (void)in_sizes; (void)n_in; (void)out_size;
}

// round 16
// speedup vs baseline: 1.2495x; 1.2495x over previous
#include <cuda_runtime.h>
#include <cuda_fp16.h>
#include <math.h>
#include <stdint.h>

// ---------------- problem constants ----------------
#define LNUM 4
#define BB   4
#define TT   2048
#define DD   1024
#define HH   1024
#define FF   256
#define MTOT (BB*TT)          // 8192
#define NCHUNK 16
#define CL   (TT/NCHUNK)      // 128

// ---------------- mma GEMM config (R13 config: 128x128, BKC=64, 2 stages) ----------------
#define BKC   64                      // k elements per stage
#define MATB  (128*128)               // 128 rows x 128B (swizzled)
#define STAGEB (3*MATB)               // Ah, Al, W = 48 KB
#define NSTG  2
#define SMEMB (NSTG*STAGEB)           // 98304 B -> 2 CTAs/SM
#define QS    72                      // fused-GLU smem staging stride (floats)
#define SS    132                     // Bu-scan smem staging stride (floats)

typedef __half f16;

// ---------------- scratch (device globals; no allocs allowed) ----------------
__device__ __align__(16) f16   g_xn_h[MTOT*DD];
__device__ __align__(16) f16   g_xn_l[MTOT*DD];
__device__ __align__(16) f16   g_in_h[MTOT*FF];
__device__ __align__(16) f16   g_in_l[MTOT*FF];
__device__ __align__(16) f16   g_bu[MTOT*2*HH];      // fp16 now
__device__ __align__(16) f16   g_hs_h[MTOT*2*HH];
__device__ __align__(16) f16   g_y_h[MTOT*DD];
__device__ __align__(16) f16   g_win[DD*FF];
__device__ __align__(16) f16   g_bw[LNUM*2*HH*DD];
__device__ __align__(16) f16   g_cw[LNUM*DD*2*HH];
__device__ __align__(16) f16   g_gw[LNUM*2*DD*DD];
__device__ float g_lam_re[LNUM*HH];
__device__ float g_lam_im[LNUM*HH];
__device__ float g_gam  [LNUM*HH];
__device__ float g_sum_re[BB*NCHUNK*HH];
__device__ float g_sum_im[BB*NCHUNK*HH];
__device__ float g_car_re[BB*NCHUNK*HH];
__device__ float g_car_im[BB*NCHUNK*HH];

// ---------------- helpers ----------------
__device__ __forceinline__ float gelu_exact(float v) {
    return 0.5f * v * (1.0f + erff(v * 0.70710678118654752f));
}
__device__ __forceinline__ void split2h(float v, f16& h, f16& l) {
    h = __float2half_rn(v);
    l = __float2half_rn(v - __half2float(h));
}
__device__ __forceinline__ void cp16(uint32_t d, const void* s) {
    asm volatile("cp.async.cg.shared.global [%0], [%1], 16;" :: "r"(d), "l"(s));
}
__device__ __forceinline__ void cpcommit() {
    asm volatile("cp.async.commit_group;" ::: "memory");
}
template<int N> __device__ __forceinline__ void cpwait() {
    asm volatile("cp.async.wait_group %0;" :: "n"(N) : "memory");
}
__device__ __forceinline__ void mma_f16(float* c, const uint32_t* a,
                                        uint32_t b0, uint32_t b1) {
    asm volatile("mma.sync.aligned.m16n8k16.row.col.f32.f16.f16.f32 "
        "{%0,%1,%2,%3}, {%4,%5,%6,%7}, {%8,%9}, {%0,%1,%2,%3};"
        : "+f"(c[0]), "+f"(c[1]), "+f"(c[2]), "+f"(c[3])
        : "r"(a[0]), "r"(a[1]), "r"(a[2]), "r"(a[3]), "r"(b0), "r"(b1));
}
__device__ __forceinline__ void ldm4(uint32_t* r, uint32_t a) {
    asm volatile("ldmatrix.sync.aligned.m8n8.x4.shared.b16 {%0,%1,%2,%3}, [%4];"
        : "=r"(r[0]), "=r"(r[1]), "=r"(r[2]), "=r"(r[3]) : "r"(a));
}

// swizzled chunk offset: row r (128B rows), 16B-chunk c (0..7)
__device__ __forceinline__ uint32_t swz(int r, int c) {
    return (uint32_t)(r * 128 + ((c ^ (r & 7)) << 4));
}

// load one K-stage: Ah (+Al if two) rows m0.., W rows n0..  (128 rows x 128B each)
__device__ __forceinline__ void ldstage(uint32_t sb, int slot,
        const f16* Ah, const f16* Al, int lda,
        const f16* W, int ldw,
        int m0, int n0, int kb, int tid, bool two) {
    uint32_t st = sb + (uint32_t)slot * STAGEB;
    #pragma unroll
    for (int j = 0; j < 4; j++) {
        int chunk = tid + j * 256;
        int row   = chunk >> 3;
        int c     = chunk & 7;
        uint32_t d = st + swz(row, c);
        int ke = kb + c * 8;
        cp16(d,           Ah + (size_t)(m0+row)*lda + ke);
        if (two) cp16(d + MATB, Al + (size_t)(m0+row)*lda + ke);
        cp16(d + 2*MATB,  W  + (size_t)(n0+row)*ldw + ke);
    }
    cpcommit();
}

// ---------------- split-fp16 tensor-core GEMM ----------------
// C[m,n] = sum_k A[m,k]*W[n,k];  A = Ah(+Al if Al!=null), W = fp16 (rn)
// epi 0: Cf = acc + bias0(n)
// epi 2: Ch = half(gelu(acc + (epi_mh+epi_ml)[m,n]*epi_n[n]))
// epi 3: fused GLU: W interleaved [w1|w2] per 128-tile; x += (a+b1)*sigmoid(q+b2)
// epi 4: Bu + chunk-scan: W interleaved [re|im] per 128-tile; Ch = half(acc*gamma),
//        then 128-step chunk scan over rows (fp32 staging) -> g_sum_re/im
__global__ __launch_bounds__(256, 2)
void gemm_mma(const f16* __restrict__ Ah, const f16* __restrict__ Al, int lda,
              const f16* __restrict__ W,
              float* __restrict__ Cf, f16* __restrict__ Ch,
              int ldc, int K, int epi,
              const float* __restrict__ bias0, const float* __restrict__ bias1,
              const f16* __restrict__ epi_mh, const f16* __restrict__ epi_ml,
              const float* __restrict__ epi_n, int loff) {
    extern __shared__ __align__(16) char smc[];
    uint32_t sb = (uint32_t)__cvta_generic_to_shared(smc);
    const int tid  = threadIdx.x;
    const int wid  = tid >> 5, lane = tid & 31;
    const int g    = lane >> 2, t2 = lane & 3;
    const int warpM = wid & 3;
    const int warpN = wid >> 2;
    const int m0 = blockIdx.y * 128;
    const int n0 = blockIdx.x * 128;
    const int NCH = K / BKC;
    const bool twopass = (Al != nullptr);

    // ldmatrix per-lane rows / chunk bases
    const int grp = lane >> 3, rr = lane & 7;
    const int cA0 = grp >> 1;
    const int cB0 = grp & 1;
    int  rA[2], rB[4];
    #pragma unroll
    for (int mt = 0; mt < 2; mt++) rA[mt] = warpM*32 + mt*16 + rr + (grp & 1)*8;
    #pragma unroll
    for (int ntp = 0; ntp < 4; ntp++) rB[ntp] = warpN*64 + ntp*16 + rr + (grp >> 1)*8;

    float acc[2][8][4];
    #pragma unroll
    for (int i = 0; i < 2; i++)
        #pragma unroll
        for (int j = 0; j < 8; j++)
            #pragma unroll
            for (int q = 0; q < 4; q++) acc[i][j][q] = 0.f;

    ldstage(sb, 0, Ah, Al, lda, W, K, m0, n0, 0,   tid, twopass);
    ldstage(sb, 1, Ah, Al, lda, W, K, m0, n0, BKC, tid, twopass);
    cpwait<1>();
    __syncthreads();

    for (int t = 0; t < NCH; t++) {
        const int slot = t & 1;
        uint32_t st   = sb + (uint32_t)slot * STAGEB;
        uint32_t Ah_s = st, Al_s = st + MATB, W_s = st + 2*MATB;

        #pragma unroll
        for (int kh = 0; kh < 4; kh++) {
            uint32_t ah[2][4], al[2][4];
            #pragma unroll
            for (int mt = 0; mt < 2; mt++) {
                uint32_t ao = swz(rA[mt], cA0 + 2*kh);
                ldm4(ah[mt], Ah_s + ao);
                if (twopass) ldm4(al[mt], Al_s + ao);
            }
            #pragma unroll
            for (int ntp = 0; ntp < 4; ntp++) {
                uint32_t bo = swz(rB[ntp], cB0 + 2*kh);
                uint32_t bh[4];
                ldm4(bh, W_s + bo);
                int nt0 = ntp*2, nt1 = ntp*2 + 1;
                // pass hi
                mma_f16(acc[0][nt0], ah[0], bh[0], bh[1]);
                mma_f16(acc[1][nt0], ah[1], bh[0], bh[1]);
                mma_f16(acc[0][nt1], ah[0], bh[2], bh[3]);
                mma_f16(acc[1][nt1], ah[1], bh[2], bh[3]);
                // pass lo
                if (twopass) {
                    mma_f16(acc[0][nt0], al[0], bh[0], bh[1]);
                    mma_f16(acc[1][nt0], al[1], bh[0], bh[1]);
                    mma_f16(acc[0][nt1], al[0], bh[2], bh[3]);
                    mma_f16(acc[1][nt1], al[1], bh[2], bh[3]);
                }
            }
        }

        // WAR guard: all warps must finish reading this slot before refill
        __syncthreads();
        if (t + 2 < NCH)
            ldstage(sb, slot, Ah, Al, lda, W, K, m0, n0, (t+2)*BKC, tid, twopass);
        else
            cpcommit();
        cpwait<1>();       // stage t+1 resident
        __syncthreads();   // publish stage t+1 CTA-wide
    }

    // ---- epilogue ----
    if (epi == 4) {
        // Bu (gamma-scaled, interleaved re/im columns) fp16 out + in-tile chunk scan
        const int j = n0 >> 7;
        float* sm = (float*)smc;
        #pragma unroll
        for (int mt = 0; mt < 2; mt++)
            #pragma unroll
            for (int nt = 0; nt < 8; nt++) {
                int r0 = warpM*32 + mt*16 + g, r1 = r0 + 8;
                int nn = warpN*64 + nt*8 + t2*2;
                int hI = j*64 + (nn & 63);
                float e0 = epi_n[hI], e1 = epi_n[hI + 1];
                float c0 = acc[mt][nt][0]*e0, c1 = acc[mt][nt][1]*e1;
                float c2 = acc[mt][nt][2]*e0, c3 = acc[mt][nt][3]*e1;
                __half2 p0(__float2half_rn(c0), __float2half_rn(c1));
                __half2 p1(__float2half_rn(c2), __float2half_rn(c3));
                *(uint32_t*)(Ch + (size_t)(m0 + r0) * ldc + n0 + nn) = *(uint32_t*)&p0;
                *(uint32_t*)(Ch + (size_t)(m0 + r1) * ldc + n0 + nn) = *(uint32_t*)&p1;
                sm[r0*SS + nn] = c0;  sm[r0*SS + nn + 1] = c1;
                sm[r1*SS + nn] = c2;  sm[r1*SS + nn + 1] = c3;
            }
        __syncthreads();
        if (tid < 64) {
            int h = j*64 + tid;
            float lre = g_lam_re[loff + h], lim = g_lam_im[loff + h];
            float are = 0.f, aim = 0.f;
            #pragma unroll 4
            for (int r = 0; r < 128; r++) {
                float ure = sm[r*SS + (tid & 63)];
                float uim = sm[r*SS + 64 + (tid & 63)];
                float nr = fmaf(are, lre, fmaf(-aim, lim, ure));
                float ni = fmaf(are, lim, fmaf(aim, lre, uim));
                are = nr; aim = ni;
            }
            int b = m0 >> 11;
            int chunk = (m0 & (TT - 1)) >> 7;
            int o = (b * NCHUNK + chunk) * HH + h;
            g_sum_re[o] = are; g_sum_im[o] = aim;
        }
        return;
    }
    if (epi == 3) {
        // fused GLU: tile cols 0-63 = w1 (a), 64-127 = w2 (q); output cols co..co+63
        const int co = blockIdx.x * 64;
        float* qs = (float*)smc;
        if (warpN == 1) {
            #pragma unroll
            for (int mt = 0; mt < 2; mt++)
                #pragma unroll
                for (int nt = 0; nt < 8; nt++) {
                    int r0 = warpM*32 + mt*16 + g, r1 = r0 + 8;
                    int c  = nt*8 + t2*2;
                    float bb0 = bias1[co + c], bb1 = bias1[co + c + 1];
                    qs[r0*QS + c]     = acc[mt][nt][0] + bb0;
                    qs[r0*QS + c + 1] = acc[mt][nt][1] + bb1;
                    qs[r1*QS + c]     = acc[mt][nt][2] + bb0;
                    qs[r1*QS + c + 1] = acc[mt][nt][3] + bb1;
                }
        }
        __syncthreads();
        if (warpN == 0) {
            #pragma unroll
            for (int mt = 0; mt < 2; mt++)
                #pragma unroll
                for (int nt = 0; nt < 8; nt++) {
                    int r0 = warpM*32 + mt*16 + g, r1 = r0 + 8;
                    int c  = nt*8 + t2*2;
                    float bb0 = bias0[co + c], bb1 = bias0[co + c + 1];
                    float a00 = acc[mt][nt][0] + bb0, a01 = acc[mt][nt][1] + bb1;
                    float a10 = acc[mt][nt][2] + bb0, a11 = acc[mt][nt][3] + bb1;
                    float q00 = qs[r0*QS + c], q01 = qs[r0*QS + c + 1];
                    float q10 = qs[r1*QS + c], q11 = qs[r1*QS + c + 1];
                    float* x0 = Cf + (size_t)(m0 + r0) * DD + co + c;
                    float* x1 = Cf + (size_t)(m0 + r1) * DD + co + c;
                    float2 v0 = *(float2*)x0, v1 = *(float2*)x1;
                    v0.x = fmaf(a00, 1.f/(1.f + expf(-q00)), v0.x);
                    v0.y = fmaf(a01, 1.f/(1.f + expf(-q01)), v0.y);
                    v1.x = fmaf(a10, 1.f/(1.f + expf(-q10)), v1.x);
                    v1.y = fmaf(a11, 1.f/(1.f + expf(-q11)), v1.y);
                    *(float2*)x0 = v0;
                    *(float2*)x1 = v1;
                }
        }
        return;
    }
    #pragma unroll
    for (int mt = 0; mt < 2; mt++) {
        #pragma unroll
        for (int nt = 0; nt < 8; nt++) {
            int row0 = m0 + warpM*32 + mt*16 + g;
            int row1 = row0 + 8;
            int col  = n0 + warpN*64 + nt*8 + t2*2;
            float c0 = acc[mt][nt][0], c1 = acc[mt][nt][1];
            float c2 = acc[mt][nt][2], c3 = acc[mt][nt][3];
            if (epi == 0) {
                float b0v = bias0[col], b1v = bias0[col + 1];
                *(float2*)(Cf + (size_t)row0 * ldc + col) = make_float2(c0 + b0v, c1 + b1v);
                *(float2*)(Cf + (size_t)row1 * ldc + col) = make_float2(c2 + b0v, c3 + b1v);
            } else {
                float d0 = epi_n[col], d1 = epi_n[col+1];
                __half2 xh0 = *(const __half2*)(epi_mh + (size_t)row0 * DD + col);
                __half2 xl0 = *(const __half2*)(epi_ml + (size_t)row0 * DD + col);
                __half2 xh1 = *(const __half2*)(epi_mh + (size_t)row1 * DD + col);
                __half2 xl1 = *(const __half2*)(epi_ml + (size_t)row1 * DD + col);
                float m00 = __half2float(xh0.x) + __half2float(xl0.x);
                float m01 = __half2float(xh0.y) + __half2float(xl0.y);
                float m10 = __half2float(xh1.x) + __half2float(xl1.x);
                float m11 = __half2float(xh1.y) + __half2float(xl1.y);
                float v0 = gelu_exact(c0 + m00 * d0);
                float v1 = gelu_exact(c1 + m01 * d1);
                float v2 = gelu_exact(c2 + m10 * d0);
                float v3 = gelu_exact(c3 + m11 * d1);
                __half2 ph0(__float2half_rn(v0), __float2half_rn(v1));
                __half2 ph1(__float2half_rn(v2), __float2half_rn(v3));
                *(uint32_t*)(Ch + (size_t)row0 * ldc + col) = *(uint32_t*)&ph0;
                *(uint32_t*)(Ch + (size_t)row1 * ldc + col) = *(uint32_t*)&ph1;
            }
        }
    }
}

// ---------------- parameter prep ----------------
__global__ void prep_kernel(const float* __restrict__ nu_log,
                            const float* __restrict__ theta_log) {
    int i = blockIdx.x * blockDim.x + threadIdx.x;
    float nu = expf(nu_log[i]);
    float th = expf(theta_log[i]);
    float r  = expf(-nu);
    g_lam_re[i] = r * cosf(th);
    g_lam_im[i] = r * sinf(th);
    g_gam[i]    = sqrtf(1.0f - expf(-2.0f * nu) + 1e-5f);
}

// ---------------- input splitter ----------------
__global__ void split_in_kernel(const float* __restrict__ s) {
    int i = blockIdx.x * 256 + threadIdx.x;
    f16 h, l;
    split2h(s[i], h, l);
    g_in_h[i] = h; g_in_l[i] = l;
}

// ---------------- all-weights converter (single fp16 plane) ----------------
#define NW  (DD*FF)
#define NB  (LNUM*2*HH*DD)
#define NC  (LNUM*DD*2*HH)
#define NG  (LNUM*2*DD*DD)
__global__ void split_wts_kernel(const float* __restrict__ W_in,
                                 const float* __restrict__ B_re,
                                 const float* __restrict__ B_im,
                                 const float* __restrict__ C_re,
                                 const float* __restrict__ C_im,
                                 const float* __restrict__ w1,
                                 const float* __restrict__ w2) {
    int idx = blockIdx.x * 256 + threadIdx.x;
    float v;
    if (idx < NW) {
        g_win[idx] = __float2half_rn(W_in[idx]);
        return;
    }
    idx -= NW;
    if (idx < NB) {
        int l_ = idx / (2*HH*DD);
        int t  = idx - l_ * (2*HH*DD);
        int np = t >> 10, c = t & 1023;
        int j = np >> 7, o = np & 127;
        if (o < 64) v = B_re[(size_t)l_*HH*DD + (j*64 + o)*DD + c];
        else        v = B_im[(size_t)l_*HH*DD + (j*64 + o - 64)*DD + c];
        g_bw[idx] = __float2half_rn(v);
        return;
    }
    idx -= NB;
    if (idx < NC) {
        int l_ = idx / (DD*2*HH);
        int t  = idx - l_ * (DD*2*HH);
        int r  = t >> 11, k = t & 2047;
        int j = k >> 7, o = k & 127;
        if (o < 64) v = C_re[(size_t)l_*DD*HH + r*HH + (j*64 + o)];
        else        v = -C_im[(size_t)l_*DD*HH + r*HH + (j*64 + o - 64)];
        g_cw[idx] = __float2half_rn(v);
        return;
    }
    idx -= NC;
    {
        int l_ = idx / (2*DD*DD);
        int t  = idx - l_ * (2*DD*DD);
        int np = t >> 10, c = t & 1023;
        int blk = np >> 7, off = np & 127;
        if (off < 64) v = w1[(size_t)l_*DD*DD + (blk*64 + off)*DD + c];
        else          v = w2[(size_t)l_*DD*DD + (blk*64 + off - 64)*DD + c];
        g_gw[idx] = __float2half_rn(v);
    }
}

// ---------------- layernorm (fp16 split outputs only) ----------------
__global__ void ln_kernel(const float* __restrict__ x,
                          const float* __restrict__ sc,
                          const float* __restrict__ bi,
                          f16* __restrict__ oh, f16* __restrict__ ol) {
    __shared__ float red[16];
    int row = blockIdx.x;
    int tid = threadIdx.x;
    const float* xr = x + (size_t)row * DD;
    float4 v = *(const float4*)(xr + tid * 4);
    float s  = v.x + v.y + v.z + v.w;
    float ss = v.x*v.x + v.y*v.y + v.z*v.z + v.w*v.w;
    #pragma unroll
    for (int off = 16; off; off >>= 1) {
        s  += __shfl_xor_sync(0xffffffffu, s,  off);
        ss += __shfl_xor_sync(0xffffffffu, ss, off);
    }
    int wid = tid >> 5;
    if ((tid & 31) == 0) { red[wid] = s; red[8 + wid] = ss; }
    __syncthreads();
    float S = 0.f, SS_ = 0.f;
    #pragma unroll
    for (int w = 0; w < 8; w++) { S += red[w]; SS_ += red[8 + w]; }
    float mu  = S * (1.0f / DD);
    float var = SS_ * (1.0f / DD) - mu * mu;
    float rstd = rsqrtf(var + 1e-5f);
    float4 s4 = *(const float4*)(sc + tid * 4);
    float4 b4 = *(const float4*)(bi + tid * 4);
    float ov[4];
    ov[0] = (v.x - mu) * rstd * s4.x + b4.x;
    ov[1] = (v.y - mu) * rstd * s4.y + b4.y;
    ov[2] = (v.z - mu) * rstd * s4.z + b4.z;
    ov[3] = (v.w - mu) * rstd * s4.w + b4.w;
    f16 h[4], l[4];
    #pragma unroll
    for (int j = 0; j < 4; j++) split2h(ov[j], h[j], l[j]);
    *(uint2*)(oh + (size_t)row * DD + tid * 4) = *(uint2*)h;
    *(uint2*)(ol + (size_t)row * DD + tid * 4) = *(uint2*)l;
}

// ---------------- scan carry (over chunk summaries) ----------------
__global__ void scan_carry_kernel(int loff) {
    int idx = blockIdx.x * blockDim.x + threadIdx.x;
    int b = idx >> 10, h = idx & (HH - 1);
    float lre = g_lam_re[loff + h], lim = g_lam_im[loff + h];
    float pre = lre, pim = lim;
    #pragma unroll
    for (int i = 0; i < 7; i++) {
        float nr = pre*pre - pim*pim;
        float ni = 2.f*pre*pim;
        pre = nr; pim = ni;
    }
    float cre = 0.f, cim = 0.f;
    #pragma unroll
    for (int c = 0; c < NCHUNK; c++) {
        int o = (b * NCHUNK + c) * HH + h;
        g_car_re[o] = cre; g_car_im[o] = cim;
        float sre = g_sum_re[o], sim = g_sum_im[o];
        float nr = cre*pre - cim*pim + sre;
        float ni = cre*pim + cim*pre + sim;
        cre = nr; cim = ni;
    }
}

// ---------------- scan apply (fp16 bu, interleaved layout; fp16 hs plane) ----------------
__global__ void scan_apply_kernel(const f16* __restrict__ bu,
                                  f16* __restrict__ hsh, int loff) {
    int h = blockIdx.x * blockDim.x + threadIdx.x;
    int c = blockIdx.y, b = blockIdx.z;
    float lre = g_lam_re[loff + h], lim = g_lam_im[loff + h];
    int o = (b * NCHUNK + c) * HH + h;
    float are = g_car_re[o], aim = g_car_im[o];
    int col = ((h >> 6) << 7) + (h & 63);   // interleaved re col; im at +64
    size_t base = ((size_t)(b * TT + c * CL)) * (2 * HH) + col;
    #pragma unroll 4
    for (int j = 0; j < CL; j++) {
        float ure = __half2float(bu[base]);
        float uim = __half2float(bu[base + 64]);
        float nr = fmaf(are, lre, fmaf(-aim, lim, ure));
        float ni = fmaf(are, lim, fmaf(aim, lre, uim));
        are = nr; aim = ni;
        hsh[base]      = __float2half_rn(are);
        hsh[base + 64] = __float2half_rn(aim);
        base += 2 * HH;
    }
}

// ---------------- launch ----------------
extern "C" void kernel_launch(void* const* d_in, const int* in_sizes, int n_in,
                              void* d_out, int out_size) {
    const float* inputs    = (const float*)d_in[0];
    const float* W_in      = (const float*)d_in[1];
    const float* b_in      = (const float*)d_in[2];
    const float* nu_log    = (const float*)d_in[3];
    const float* theta_log = (const float*)d_in[4];
    const float* B_re      = (const float*)d_in[5];
    const float* B_im      = (const float*)d_in[6];
    const float* C_re      = (const float*)d_in[7];
    const float* C_im      = (const float*)d_in[8];
    const float* D_diag    = (const float*)d_in[9];
    const float* ln_scale  = (const float*)d_in[10];
    const float* ln_bias   = (const float*)d_in[11];
    const float* w1        = (const float*)d_in[12];
    const float* b1        = (const float*)d_in[13];
    const float* w2        = (const float*)d_in[14];
    const float* b2        = (const float*)d_in[15];
    float* x = (float*)d_out;

    cudaFuncSetAttribute(gemm_mma, cudaFuncAttributeMaxDynamicSharedMemorySize, SMEMB);

    float *p_gam;
    f16 *p_bu, *p_xnh, *p_xnl, *p_inh, *p_inl, *p_hsh, *p_yh;
    f16 *p_win, *p_bw, *p_cw, *p_gw;
    cudaGetSymbolAddress((void**)&p_bu,  g_bu);
    cudaGetSymbolAddress((void**)&p_gam, g_gam);
    cudaGetSymbolAddress((void**)&p_xnh, g_xn_h);
    cudaGetSymbolAddress((void**)&p_xnl, g_xn_l);
    cudaGetSymbolAddress((void**)&p_inh, g_in_h);
    cudaGetSymbolAddress((void**)&p_inl, g_in_l);
    cudaGetSymbolAddress((void**)&p_hsh, g_hs_h);
    cudaGetSymbolAddress((void**)&p_yh,  g_y_h);
    cudaGetSymbolAddress((void**)&p_win, g_win);
    cudaGetSymbolAddress((void**)&p_bw,  g_bw);
    cudaGetSymbolAddress((void**)&p_cw,  g_cw);
    cudaGetSymbolAddress((void**)&p_gw,  g_gw);

    // params, split inputs, convert all weights
    prep_kernel<<<(LNUM * HH) / 256, 256>>>(nu_log, theta_log);
    split_in_kernel<<<(MTOT*FF)/256, 256>>>(inputs);
    split_wts_kernel<<<(NW + NB + NC + NG)/256, 256>>>(
        W_in, B_re, B_im, C_re, C_im, w1, w2);

    // input projection: x = inputs @ W_in^T + b_in  (2-pass)
    gemm_mma<<<dim3(DD/128, MTOT/128), 256, SMEMB>>>(
        p_inh, p_inl, FF, p_win,
        x, nullptr, DD, FF, 0,
        b_in, nullptr, nullptr, nullptr, nullptr, 0);

    for (int l = 0; l < LNUM; l++) {
        // layernorm -> fp16 split planes
        ln_kernel<<<MTOT, 256>>>(x, ln_scale + l*DD, ln_bias + l*DD, p_xnh, p_xnl);

        // Bu = gamma * (xn @ Bw^T) with fused chunk-scan summaries (2-pass, fp16 bu out)
        gemm_mma<<<dim3(2*HH/128, MTOT/128), 256, SMEMB>>>(
            p_xnh, p_xnl, DD,
            p_bw + (size_t)l*2*HH*DD,
            nullptr, p_bu, 2*HH, DD, 4,
            nullptr, nullptr, nullptr, nullptr, p_gam + l*HH, l*HH);

        scan_carry_kernel<<<(BB*HH)/256, 256>>>(l*HH);
        scan_apply_kernel<<<dim3(HH/256, NCHUNK, BB), 256>>>(p_bu, p_hsh, l*HH);

        // y = gelu( hs @ Cw^T + xn * D_diag )  (1-pass, fp16 out)
        gemm_mma<<<dim3(DD/128, MTOT/128), 256, SMEMB>>>(
            p_hsh, nullptr, 2*HH,
            p_cw + (size_t)l*DD*2*HH,
            nullptr, p_yh, DD, 2*HH, 2,
            nullptr, nullptr, p_xnh, p_xnl, D_diag + l*DD, 0);

        // fused GLU + residual (1-pass): x += (y@w1^T + b1) * sigmoid(y@w2^T + b2)
        gemm_mma<<<dim3(2*DD/128, MTOT/128), 256, SMEMB>>>(
            p_yh, nullptr, DD,
            p_gw + (size_t)l*2*DD*DD,
            x, nullptr, DD, DD, 3,
            b1 + l*DD, b2 + l*DD, nullptr, nullptr, nullptr, 0);
    }
    (void)in_sizes; (void)n_in; (void)out_size;
}

// round 17
// speedup vs baseline: 1.5894x; 1.2720x over previous
#include <cuda_runtime.h>
#include <cuda_fp16.h>
#include <math.h>
#include <stdint.h>

// ---------------- problem constants ----------------
#define LNUM 4
#define BB   4
#define TT   2048
#define DD   1024
#define HH   1024
#define FF   256
#define MTOT (BB*TT)          // 8192
#define NCHUNK 16
#define CL   (TT/NCHUNK)      // 128

// ---------------- mma GEMM config ----------------
#define BKC   64                      // k elements per stage
#define MATB  (128*128)               // 128 rows x 128B (swizzled)
#define SMEMB 98304                   // 96 KB -> 2 CTAs/SM
#define QS    72                      // fused-GLU smem staging stride (floats)
#define SS    132                     // Bu-scan smem staging stride (floats)

typedef __half f16;

// ---------------- scratch (device globals; no allocs allowed) ----------------
__device__ __align__(16) f16   g_xn_h[MTOT*DD];
__device__ __align__(16) f16   g_xn_l[MTOT*DD];
__device__ __align__(16) f16   g_in_h[MTOT*FF];
__device__ __align__(16) f16   g_in_l[MTOT*FF];
__device__ __align__(16) f16   g_bu[MTOT*2*HH];
__device__ __align__(16) f16   g_hs_h[MTOT*2*HH];
__device__ __align__(16) f16   g_y_h[MTOT*DD];
__device__ __align__(16) f16   g_win[DD*FF];
__device__ __align__(16) f16   g_bw[LNUM*2*HH*DD];
__device__ __align__(16) f16   g_cw[LNUM*DD*2*HH];
__device__ __align__(16) f16   g_gw[LNUM*2*DD*DD];
__device__ float g_lam_re[LNUM*HH];
__device__ float g_lam_im[LNUM*HH];
__device__ float g_gam  [LNUM*HH];
__device__ float g_sum_re[BB*NCHUNK*HH];
__device__ float g_sum_im[BB*NCHUNK*HH];
__device__ float g_car_re[BB*NCHUNK*HH];
__device__ float g_car_im[BB*NCHUNK*HH];

// ---------------- helpers ----------------
__device__ __forceinline__ float gelu_exact(float v) {
    return 0.5f * v * (1.0f + erff(v * 0.70710678118654752f));
}
__device__ __forceinline__ void split2h(float v, f16& h, f16& l) {
    h = __float2half_rn(v);
    l = __float2half_rn(v - __half2float(h));
}
__device__ __forceinline__ void cp16(uint32_t d, const void* s) {
    asm volatile("cp.async.cg.shared.global [%0], [%1], 16;" :: "r"(d), "l"(s));
}
__device__ __forceinline__ void cpcommit() {
    asm volatile("cp.async.commit_group;" ::: "memory");
}
template<int N> __device__ __forceinline__ void cpwait() {
    asm volatile("cp.async.wait_group %0;" :: "n"(N) : "memory");
}
__device__ __forceinline__ void mma_f16(float* c, const uint32_t* a,
                                        uint32_t b0, uint32_t b1) {
    asm volatile("mma.sync.aligned.m16n8k16.row.col.f32.f16.f16.f32 "
        "{%0,%1,%2,%3}, {%4,%5,%6,%7}, {%8,%9}, {%0,%1,%2,%3};"
        : "+f"(c[0]), "+f"(c[1]), "+f"(c[2]), "+f"(c[3])
        : "r"(a[0]), "r"(a[1]), "r"(a[2]), "r"(a[3]), "r"(b0), "r"(b1));
}
__device__ __forceinline__ void ldm4(uint32_t* r, uint32_t a) {
    asm volatile("ldmatrix.sync.aligned.m8n8.x4.shared.b16 {%0,%1,%2,%3}, [%4];"
        : "=r"(r[0]), "=r"(r[1]), "=r"(r[2]), "=r"(r[3]) : "r"(a));
}

// swizzled chunk offset: row r (128B rows), 16B-chunk c (0..7)
__device__ __forceinline__ uint32_t swz(int r, int c) {
    return (uint32_t)(r * 128 + ((c ^ (r & 7)) << 4));
}

// load one K-stage. 2-pass stage: [Ah|Al|W] (48KB); 1-pass stage: [Ah|W] (32KB)
template<bool TWO>
__device__ __forceinline__ void ldstage(uint32_t sb, int slot,
        const f16* Ah, const f16* Al, int lda,
        const f16* W, int ldw,
        int m0, int n0, int kb, int tid) {
    constexpr uint32_t STG = TWO ? 3*MATB : 2*MATB;
    constexpr uint32_t WOFF = TWO ? 2*MATB : MATB;
    uint32_t st = sb + (uint32_t)slot * STG;
    #pragma unroll
    for (int j = 0; j < 4; j++) {
        int chunk = tid + j * 256;
        int row   = chunk >> 3;
        int c     = chunk & 7;
        uint32_t d = st + swz(row, c);
        int ke = kb + c * 8;
        cp16(d, Ah + (size_t)(m0+row)*lda + ke);
        if (TWO) cp16(d + MATB, Al + (size_t)(m0+row)*lda + ke);
        cp16(d + WOFF, W + (size_t)(n0+row)*ldw + ke);
    }
    cpcommit();
}

// ---------------- split-fp16 tensor-core GEMM ----------------
// TWO=true: A = Ah+Al 2-pass, NSTG=2. TWO=false: A = Ah 1-pass, NSTG=3 (deeper slack).
// epi 0: Cf = acc + bias0(n)
// epi 2: Ch = half(gelu(acc + (epi_mh+epi_ml)[m,n]*epi_n[n]))
// epi 3: fused GLU: W interleaved [w1|w2] per 128-tile; x += (a+b1)*sigmoid(q+b2)
// epi 4: Bu + chunk-scan: W interleaved [re|im] per 128-tile; Ch = half(acc*gamma), scan->g_sum
template<bool TWO>
__global__ __launch_bounds__(256, 2)
void gemm_mma(const f16* __restrict__ Ah, const f16* __restrict__ Al, int lda,
              const f16* __restrict__ W,
              float* __restrict__ Cf, f16* __restrict__ Ch,
              int ldc, int K, int epi,
              const float* __restrict__ bias0, const float* __restrict__ bias1,
              const f16* __restrict__ epi_mh, const f16* __restrict__ epi_ml,
              const float* __restrict__ epi_n, int loff) {
    extern __shared__ __align__(16) char smc[];
    uint32_t sb = (uint32_t)__cvta_generic_to_shared(smc);
    constexpr int NSTG = TWO ? 2 : 3;
    constexpr uint32_t STG  = TWO ? 3*MATB : 2*MATB;
    constexpr uint32_t WOFF = TWO ? 2*MATB : MATB;
    const int tid  = threadIdx.x;
    const int wid  = tid >> 5, lane = tid & 31;
    const int g    = lane >> 2, t2 = lane & 3;
    const int warpM = wid & 3;
    const int warpN = wid >> 2;
    const int m0 = blockIdx.y * 128;
    const int n0 = blockIdx.x * 128;
    const int NCH = K / BKC;

    const int grp = lane >> 3, rr = lane & 7;
    const int cA0 = grp >> 1;
    const int cB0 = grp & 1;
    int  rA[2], rB[4];
    #pragma unroll
    for (int mt = 0; mt < 2; mt++) rA[mt] = warpM*32 + mt*16 + rr + (grp & 1)*8;
    #pragma unroll
    for (int ntp = 0; ntp < 4; ntp++) rB[ntp] = warpN*64 + ntp*16 + rr + (grp >> 1)*8;

    float acc[2][8][4];
    #pragma unroll
    for (int i = 0; i < 2; i++)
        #pragma unroll
        for (int j = 0; j < 8; j++)
            #pragma unroll
            for (int q = 0; q < 4; q++) acc[i][j][q] = 0.f;

    // prologue: fill all NSTG slots
    #pragma unroll
    for (int s = 0; s < NSTG; s++)
        ldstage<TWO>(sb, s, Ah, Al, lda, W, K, m0, n0, s*BKC, tid);
    cpwait<NSTG-1>();
    __syncthreads();

    int slot = 0;
    for (int t = 0; t < NCH; t++) {
        uint32_t st   = sb + (uint32_t)slot * STG;
        uint32_t Ah_s = st, Al_s = st + MATB, W_s = st + WOFF;

        #pragma unroll
        for (int kh = 0; kh < 4; kh++) {
            uint32_t ah[2][4], al[2][4];
            #pragma unroll
            for (int mt = 0; mt < 2; mt++) {
                uint32_t ao = swz(rA[mt], cA0 + 2*kh);
                ldm4(ah[mt], Ah_s + ao);
                if (TWO) ldm4(al[mt], Al_s + ao);
            }
            #pragma unroll
            for (int ntp = 0; ntp < 4; ntp++) {
                uint32_t bo = swz(rB[ntp], cB0 + 2*kh);
                uint32_t bh[4];
                ldm4(bh, W_s + bo);
                int nt0 = ntp*2, nt1 = ntp*2 + 1;
                mma_f16(acc[0][nt0], ah[0], bh[0], bh[1]);
                mma_f16(acc[1][nt0], ah[1], bh[0], bh[1]);
                mma_f16(acc[0][nt1], ah[0], bh[2], bh[3]);
                mma_f16(acc[1][nt1], ah[1], bh[2], bh[3]);
                if (TWO) {
                    mma_f16(acc[0][nt0], al[0], bh[0], bh[1]);
                    mma_f16(acc[1][nt0], al[1], bh[0], bh[1]);
                    mma_f16(acc[0][nt1], al[0], bh[2], bh[3]);
                    mma_f16(acc[1][nt1], al[1], bh[2], bh[3]);
                }
            }
        }

        // WAR guard: all warps done reading this slot before it is refilled
        __syncthreads();
        if (t + NSTG < NCH)
            ldstage<TWO>(sb, slot, Ah, Al, lda, W, K, m0, n0, (t+NSTG)*BKC, tid);
        else
            cpcommit();
        cpwait<NSTG-1>();   // stage t+1 resident
        __syncthreads();    // publish stage t+1 CTA-wide
        slot = (slot + 1 == NSTG) ? 0 : slot + 1;
    }

    // ---- epilogue ----
    if (epi == 4) {
        // Bu (gamma-scaled, interleaved re/im columns) fp16 out + in-tile chunk scan
        const int j = n0 >> 7;
        float* sm = (float*)smc;
        #pragma unroll
        for (int mt = 0; mt < 2; mt++)
            #pragma unroll
            for (int nt = 0; nt < 8; nt++) {
                int r0 = warpM*32 + mt*16 + g, r1 = r0 + 8;
                int nn = warpN*64 + nt*8 + t2*2;
                int hI = j*64 + (nn & 63);
                float e0 = epi_n[hI], e1 = epi_n[hI + 1];
                float c0 = acc[mt][nt][0]*e0, c1 = acc[mt][nt][1]*e1;
                float c2 = acc[mt][nt][2]*e0, c3 = acc[mt][nt][3]*e1;
                __half2 p0(__float2half_rn(c0), __float2half_rn(c1));
                __half2 p1(__float2half_rn(c2), __float2half_rn(c3));
                *(uint32_t*)(Ch + (size_t)(m0 + r0) * ldc + n0 + nn) = *(uint32_t*)&p0;
                *(uint32_t*)(Ch + (size_t)(m0 + r1) * ldc + n0 + nn) = *(uint32_t*)&p1;
                sm[r0*SS + nn] = c0;  sm[r0*SS + nn + 1] = c1;
                sm[r1*SS + nn] = c2;  sm[r1*SS + nn + 1] = c3;
            }
        __syncthreads();
        if (tid < 64) {
            int h = j*64 + tid;
            float lre = g_lam_re[loff + h], lim = g_lam_im[loff + h];
            float are = 0.f, aim = 0.f;
            #pragma unroll 4
            for (int r = 0; r < 128; r++) {
                float ure = sm[r*SS + (tid & 63)];
                float uim = sm[r*SS + 64 + (tid & 63)];
                float nr = fmaf(are, lre, fmaf(-aim, lim, ure));
                float ni = fmaf(are, lim, fmaf(aim, lre, uim));
                are = nr; aim = ni;
            }
            int b = m0 >> 11;
            int chunk = (m0 & (TT - 1)) >> 7;
            int o = (b * NCHUNK + chunk) * HH + h;
            g_sum_re[o] = are; g_sum_im[o] = aim;
        }
        return;
    }
    if (epi == 3) {
        // fused GLU: tile cols 0-63 = w1 (a), 64-127 = w2 (q); output cols co..co+63
        const int co = blockIdx.x * 64;
        float* qs = (float*)smc;
        if (warpN == 1) {
            #pragma unroll
            for (int mt = 0; mt < 2; mt++)
                #pragma unroll
                for (int nt = 0; nt < 8; nt++) {
                    int r0 = warpM*32 + mt*16 + g, r1 = r0 + 8;
                    int c  = nt*8 + t2*2;
                    float bb0 = bias1[co + c], bb1 = bias1[co + c + 1];
                    qs[r0*QS + c]     = acc[mt][nt][0] + bb0;
                    qs[r0*QS + c + 1] = acc[mt][nt][1] + bb1;
                    qs[r1*QS + c]     = acc[mt][nt][2] + bb0;
                    qs[r1*QS + c + 1] = acc[mt][nt][3] + bb1;
                }
        }
        __syncthreads();
        if (warpN == 0) {
            #pragma unroll
            for (int mt = 0; mt < 2; mt++)
                #pragma unroll
                for (int nt = 0; nt < 8; nt++) {
                    int r0 = warpM*32 + mt*16 + g, r1 = r0 + 8;
                    int c  = nt*8 + t2*2;
                    float bb0 = bias0[co + c], bb1 = bias0[co + c + 1];
                    float a00 = acc[mt][nt][0] + bb0, a01 = acc[mt][nt][1] + bb1;
                    float a10 = acc[mt][nt][2] + bb0, a11 = acc[mt][nt][3] + bb1;
                    float q00 = qs[r0*QS + c], q01 = qs[r0*QS + c + 1];
                    float q10 = qs[r1*QS + c], q11 = qs[r1*QS + c + 1];
                    float* x0 = Cf + (size_t)(m0 + r0) * DD + co + c;
                    float* x1 = Cf + (size_t)(m0 + r1) * DD + co + c;
                    float2 v0 = *(float2*)x0, v1 = *(float2*)x1;
                    v0.x = fmaf(a00, 1.f/(1.f + expf(-q00)), v0.x);
                    v0.y = fmaf(a01, 1.f/(1.f + expf(-q01)), v0.y);
                    v1.x = fmaf(a10, 1.f/(1.f + expf(-q10)), v1.x);
                    v1.y = fmaf(a11, 1.f/(1.f + expf(-q11)), v1.y);
                    *(float2*)x0 = v0;
                    *(float2*)x1 = v1;
                }
        }
        return;
    }
    #pragma unroll
    for (int mt = 0; mt < 2; mt++) {
        #pragma unroll
        for (int nt = 0; nt < 8; nt++) {
            int row0 = m0 + warpM*32 + mt*16 + g;
            int row1 = row0 + 8;
            int col  = n0 + warpN*64 + nt*8 + t2*2;
            float c0 = acc[mt][nt][0], c1 = acc[mt][nt][1];
            float c2 = acc[mt][nt][2], c3 = acc[mt][nt][3];
            if (epi == 0) {
                float b0v = bias0[col], b1v = bias0[col + 1];
                *(float2*)(Cf + (size_t)row0 * ldc + col) = make_float2(c0 + b0v, c1 + b1v);
                *(float2*)(Cf + (size_t)row1 * ldc + col) = make_float2(c2 + b0v, c3 + b1v);
            } else {
                float d0 = epi_n[col], d1 = epi_n[col+1];
                __half2 xh0 = *(const __half2*)(epi_mh + (size_t)row0 * DD + col);
                __half2 xl0 = *(const __half2*)(epi_ml + (size_t)row0 * DD + col);
                __half2 xh1 = *(const __half2*)(epi_mh + (size_t)row1 * DD + col);
                __half2 xl1 = *(const __half2*)(epi_ml + (size_t)row1 * DD + col);
                float m00 = __half2float(xh0.x) + __half2float(xl0.x);
                float m01 = __half2float(xh0.y) + __half2float(xl0.y);
                float m10 = __half2float(xh1.x) + __half2float(xl1.x);
                float m11 = __half2float(xh1.y) + __half2float(xl1.y);
                float v0 = gelu_exact(c0 + m00 * d0);
                float v1 = gelu_exact(c1 + m01 * d1);
                float v2 = gelu_exact(c2 + m10 * d0);
                float v3 = gelu_exact(c3 + m11 * d1);
                __half2 ph0(__float2half_rn(v0), __float2half_rn(v1));
                __half2 ph1(__float2half_rn(v2), __float2half_rn(v3));
                *(uint32_t*)(Ch + (size_t)row0 * ldc + col) = *(uint32_t*)&ph0;
                *(uint32_t*)(Ch + (size_t)row1 * ldc + col) = *(uint32_t*)&ph1;
            }
        }
    }
}

// ---------------- parameter prep ----------------
__global__ void prep_kernel(const float* __restrict__ nu_log,
                            const float* __restrict__ theta_log) {
    int i = blockIdx.x * blockDim.x + threadIdx.x;
    float nu = expf(nu_log[i]);
    float th = expf(theta_log[i]);
    float r  = expf(-nu);
    g_lam_re[i] = r * cosf(th);
    g_lam_im[i] = r * sinf(th);
    g_gam[i]    = sqrtf(1.0f - expf(-2.0f * nu) + 1e-5f);
}

// ---------------- input splitter ----------------
__global__ void split_in_kernel(const float* __restrict__ s) {
    int i = blockIdx.x * 256 + threadIdx.x;
    f16 h, l;
    split2h(s[i], h, l);
    g_in_h[i] = h; g_in_l[i] = l;
}

// ---------------- all-weights converter (single fp16 plane) ----------------
#define NW  (DD*FF)
#define NB  (LNUM*2*HH*DD)
#define NC  (LNUM*DD*2*HH)
#define NG  (LNUM*2*DD*DD)
__global__ void split_wts_kernel(const float* __restrict__ W_in,
                                 const float* __restrict__ B_re,
                                 const float* __restrict__ B_im,
                                 const float* __restrict__ C_re,
                                 const float* __restrict__ C_im,
                                 const float* __restrict__ w1,
                                 const float* __restrict__ w2) {
    int idx = blockIdx.x * 256 + threadIdx.x;
    float v;
    if (idx < NW) {
        g_win[idx] = __float2half_rn(W_in[idx]);
        return;
    }
    idx -= NW;
    if (idx < NB) {
        int l_ = idx / (2*HH*DD);
        int t  = idx - l_ * (2*HH*DD);
        int np = t >> 10, c = t & 1023;
        int j = np >> 7, o = np & 127;
        if (o < 64) v = B_re[(size_t)l_*HH*DD + (j*64 + o)*DD + c];
        else        v = B_im[(size_t)l_*HH*DD + (j*64 + o - 64)*DD + c];
        g_bw[idx] = __float2half_rn(v);
        return;
    }
    idx -= NB;
    if (idx < NC) {
        int l_ = idx / (DD*2*HH);
        int t  = idx - l_ * (DD*2*HH);
        int r  = t >> 11, k = t & 2047;
        int j = k >> 7, o = k & 127;
        if (o < 64) v = C_re[(size_t)l_*DD*HH + r*HH + (j*64 + o)];
        else        v = -C_im[(size_t)l_*DD*HH + r*HH + (j*64 + o - 64)];
        g_cw[idx] = __float2half_rn(v);
        return;
    }
    idx -= NC;
    {
        int l_ = idx / (2*DD*DD);
        int t  = idx - l_ * (2*DD*DD);
        int np = t >> 10, c = t & 1023;
        int blk = np >> 7, off = np & 127;
        if (off < 64) v = w1[(size_t)l_*DD*DD + (blk*64 + off)*DD + c];
        else          v = w2[(size_t)l_*DD*DD + (blk*64 + off - 64)*DD + c];
        g_gw[idx] = __float2half_rn(v);
    }
}

// ---------------- layernorm (fp16 split outputs only) ----------------
__global__ void ln_kernel(const float* __restrict__ x,
                          const float* __restrict__ sc,
                          const float* __restrict__ bi,
                          f16* __restrict__ oh, f16* __restrict__ ol) {
    __shared__ float red[16];
    int row = blockIdx.x;
    int tid = threadIdx.x;
    const float* xr = x + (size_t)row * DD;
    float4 v = *(const float4*)(xr + tid * 4);
    float s  = v.x + v.y + v.z + v.w;
    float ss = v.x*v.x + v.y*v.y + v.z*v.z + v.w*v.w;
    #pragma unroll
    for (int off = 16; off; off >>= 1) {
        s  += __shfl_xor_sync(0xffffffffu, s,  off);
        ss += __shfl_xor_sync(0xffffffffu, ss, off);
    }
    int wid = tid >> 5;
    if ((tid & 31) == 0) { red[wid] = s; red[8 + wid] = ss; }
    __syncthreads();
    float S = 0.f, SS_ = 0.f;
    #pragma unroll
    for (int w = 0; w < 8; w++) { S += red[w]; SS_ += red[8 + w]; }
    float mu  = S * (1.0f / DD);
    float var = SS_ * (1.0f / DD) - mu * mu;
    float rstd = rsqrtf(var + 1e-5f);
    float4 s4 = *(const float4*)(sc + tid * 4);
    float4 b4 = *(const float4*)(bi + tid * 4);
    float ov[4];
    ov[0] = (v.x - mu) * rstd * s4.x + b4.x;
    ov[1] = (v.y - mu) * rstd * s4.y + b4.y;
    ov[2] = (v.z - mu) * rstd * s4.z + b4.z;
    ov[3] = (v.w - mu) * rstd * s4.w + b4.w;
    f16 h[4], l[4];
    #pragma unroll
    for (int j = 0; j < 4; j++) split2h(ov[j], h[j], l[j]);
    *(uint2*)(oh + (size_t)row * DD + tid * 4) = *(uint2*)h;
    *(uint2*)(ol + (size_t)row * DD + tid * 4) = *(uint2*)l;
}

// ---------------- scan carry (over chunk summaries) ----------------
__global__ void scan_carry_kernel(int loff) {
    int idx = blockIdx.x * blockDim.x + threadIdx.x;
    int b = idx >> 10, h = idx & (HH - 1);
    float lre = g_lam_re[loff + h], lim = g_lam_im[loff + h];
    float pre = lre, pim = lim;
    #pragma unroll
    for (int i = 0; i < 7; i++) {
        float nr = pre*pre - pim*pim;
        float ni = 2.f*pre*pim;
        pre = nr; pim = ni;
    }
    float cre = 0.f, cim = 0.f;
    #pragma unroll
    for (int c = 0; c < NCHUNK; c++) {
        int o = (b * NCHUNK + c) * HH + h;
        g_car_re[o] = cre; g_car_im[o] = cim;
        float sre = g_sum_re[o], sim = g_sum_im[o];
        float nr = cre*pre - cim*pim + sre;
        float ni = cre*pim + cim*pre + sim;
        cre = nr; cim = ni;
    }
}

// ---------------- scan apply (fp16 bu, interleaved layout; fp16 hs plane) ----------------
__global__ void scan_apply_kernel(const f16* __restrict__ bu,
                                  f16* __restrict__ hsh, int loff) {
    int h = blockIdx.x * blockDim.x + threadIdx.x;
    int c = blockIdx.y, b = blockIdx.z;
    float lre = g_lam_re[loff + h], lim = g_lam_im[loff + h];
    int o = (b * NCHUNK + c) * HH + h;
    float are = g_car_re[o], aim = g_car_im[o];
    int col = ((h >> 6) << 7) + (h & 63);   // interleaved re col; im at +64
    size_t base = ((size_t)(b * TT + c * CL)) * (2 * HH) + col;
    #pragma unroll 4
    for (int j = 0; j < CL; j++) {
        float ure = __half2float(bu[base]);
        float uim = __half2float(bu[base + 64]);
        float nr = fmaf(are, lre, fmaf(-aim, lim, ure));
        float ni = fmaf(are, lim, fmaf(aim, lre, uim));
        are = nr; aim = ni;
        hsh[base]      = __float2half_rn(are);
        hsh[base + 64] = __float2half_rn(aim);
        base += 2 * HH;
    }
}

// ---------------- launch ----------------
extern "C" void kernel_launch(void* const* d_in, const int* in_sizes, int n_in,
                              void* d_out, int out_size) {
    const float* inputs    = (const float*)d_in[0];
    const float* W_in      = (const float*)d_in[1];
    const float* b_in      = (const float*)d_in[2];
    const float* nu_log    = (const float*)d_in[3];
    const float* theta_log = (const float*)d_in[4];
    const float* B_re      = (const float*)d_in[5];
    const float* B_im      = (const float*)d_in[6];
    const float* C_re      = (const float*)d_in[7];
    const float* C_im      = (const float*)d_in[8];
    const float* D_diag    = (const float*)d_in[9];
    const float* ln_scale  = (const float*)d_in[10];
    const float* ln_bias   = (const float*)d_in[11];
    const float* w1        = (const float*)d_in[12];
    const float* b1        = (const float*)d_in[13];
    const float* w2        = (const float*)d_in[14];
    const float* b2        = (const float*)d_in[15];
    float* x = (float*)d_out;

    cudaFuncSetAttribute(gemm_mma<true>,  cudaFuncAttributeMaxDynamicSharedMemorySize, SMEMB);
    cudaFuncSetAttribute(gemm_mma<false>, cudaFuncAttributeMaxDynamicSharedMemorySize, SMEMB);

    float *p_gam;
    f16 *p_bu, *p_xnh, *p_xnl, *p_inh, *p_inl, *p_hsh, *p_yh;
    f16 *p_win, *p_bw, *p_cw, *p_gw;
    cudaGetSymbolAddress((void**)&p_bu,  g_bu);
    cudaGetSymbolAddress((void**)&p_gam, g_gam);
    cudaGetSymbolAddress((void**)&p_xnh, g_xn_h);
    cudaGetSymbolAddress((void**)&p_xnl, g_xn_l);
    cudaGetSymbolAddress((void**)&p_inh, g_in_h);
    cudaGetSymbolAddress((void**)&p_inl, g_in_l);
    cudaGetSymbolAddress((void**)&p_hsh, g_hs_h);
    cudaGetSymbolAddress((void**)&p_yh,  g_y_h);
    cudaGetSymbolAddress((void**)&p_win, g_win);
    cudaGetSymbolAddress((void**)&p_bw,  g_bw);
    cudaGetSymbolAddress((void**)&p_cw,  g_cw);
    cudaGetSymbolAddress((void**)&p_gw,  g_gw);

    prep_kernel<<<(LNUM * HH) / 256, 256>>>(nu_log, theta_log);
    split_in_kernel<<<(MTOT*FF)/256, 256>>>(inputs);
    split_wts_kernel<<<(NW + NB + NC + NG)/256, 256>>>(
        W_in, B_re, B_im, C_re, C_im, w1, w2);

    // input projection: x = inputs @ W_in^T + b_in  (2-pass)
    gemm_mma<true><<<dim3(DD/128, MTOT/128), 256, SMEMB>>>(
        p_inh, p_inl, FF, p_win,
        x, nullptr, DD, FF, 0,
        b_in, nullptr, nullptr, nullptr, nullptr, 0);

    for (int l = 0; l < LNUM; l++) {
        ln_kernel<<<MTOT, 256>>>(x, ln_scale + l*DD, ln_bias + l*DD, p_xnh, p_xnl);

        // Bu = gamma * (xn @ Bw^T) with fused chunk-scan summaries (2-pass, fp16 bu out)
        gemm_mma<true><<<dim3(2*HH/128, MTOT/128), 256, SMEMB>>>(
            p_xnh, p_xnl, DD,
            p_bw + (size_t)l*2*HH*DD,
            nullptr, p_bu, 2*HH, DD, 4,
            nullptr, nullptr, nullptr, nullptr, p_gam + l*HH, l*HH);

        scan_carry_kernel<<<(BB*HH)/256, 256>>>(l*HH);
        scan_apply_kernel<<<dim3(HH/256, NCHUNK, BB), 256>>>(p_bu, p_hsh, l*HH);

        // y = gelu( hs @ Cw^T + xn * D_diag )  (1-pass, NSTG=3, fp16 out)
        gemm_mma<false><<<dim3(DD/128, MTOT/128), 256, SMEMB>>>(
            p_hsh, nullptr, 2*HH,
            p_cw + (size_t)l*DD*2*HH,
            nullptr, p_yh, DD, 2*HH, 2,
            nullptr, nullptr, p_xnh, p_xnl, D_diag + l*DD, 0);

        // fused GLU + residual (1-pass, NSTG=3): x += (y@w1^T + b1) * sigmoid(y@w2^T + b2)
        gemm_mma<false><<<dim3(2*DD/128, MTOT/128), 256, SMEMB>>>(
            p_yh, nullptr, DD,
            p_gw + (size_t)l*2*DD*DD,
            x, nullptr, DD, DD, 3,
            b1 + l*DD, b2 + l*DD, nullptr, nullptr, nullptr, 0);
    }
    (void)in_sizes; (void)n_in; (void)out_size;
}